// round 12
// baseline (speedup 1.0000x reference)
#include <cuda_runtime.h>
#include <cuda_bf16.h>
#include <stdint.h>

#define NB   512      // batch (docs)
#define NS   512      // seq len
#define NV   50265    // vocab
#define PAD  1
#define TOT  (NB * NV)          // 25,735,680 floats, divisible by 4
#define NV4  (TOT / 4)          // 6,433,920 float4

#define FILL_BLOCKS  1184       // 148 SMs x 8 -> perfectly balanced
#define FILL_THREADS 256

// Scratch (device globals only — no allocations allowed)
__device__ int g_dl[NB];    // doc lengths (non-pad token counts)

// ---------------------------------------------------------------------------
// Kernel 1: per-row doc length. 512 blocks x 128 threads, one int4 per thread.
// ---------------------------------------------------------------------------
__global__ void __launch_bounds__(128) k_doclen(const int* __restrict__ ids) {
    int b = blockIdx.x;
    int t = threadIdx.x;
    const int4* row4 = (const int4*)(ids + b * NS);
    int4 q = row4[t];                      // 128 threads x int4 = 512 ints
    int cnt = (q.x != PAD) + (q.y != PAD) + (q.z != PAD) + (q.w != PAD);

    #pragma unroll
    for (int o = 16; o; o >>= 1)
        cnt += __shfl_down_sync(0xffffffffu, cnt, o);

    __shared__ int red[4];
    if ((t & 31) == 0) red[t >> 5] = cnt;
    __syncthreads();
    if (t == 0)
        g_dl[b] = red[0] + red[1] + red[2] + red[3];
}

// ---------------------------------------------------------------------------
// Kernel 2: balanced zero-fill of the whole output. Linear float4 grid-stride,
// no per-row head/tail (TOT % 4 == 0, base 256B-aligned). Pure store stream.
// ---------------------------------------------------------------------------
__global__ void __launch_bounds__(FILL_THREADS) k_fill(float4* __restrict__ out4) {
    const float4 z4 = make_float4(0.f, 0.f, 0.f, 0.f);
    int stride = FILL_BLOCKS * FILL_THREADS;          // 303,104
    for (int i = blockIdx.x * FILL_THREADS + threadIdx.x; i < NV4; i += stride)
        out4[i] = z4;
}

// ---------------------------------------------------------------------------
// Kernel 3: atomic histogram + BM25 transform. One block per row, 512 threads.
// Zeros are globally visible (kernel-ordering edge replaces the threadfence).
//   old = atomicAdd(&row[tok], 1.0f); leader = (old == 0)
//   sync; leader reads final count via __ldcg (L2) and writes f(count).
// ---------------------------------------------------------------------------
__global__ void __launch_bounds__(512) k_hist(const int* __restrict__ ids,
                                              float* __restrict__ out) {
    __shared__ int   red[16];
    __shared__ float s_add;

    int b = blockIdx.x;
    int t = threadIdx.x;

    int my = ids[b * NS + t];          // own token (coalesced)

    // avgdl: block-reduce the 512-entry g_dl array (L2 hits).
    int v = g_dl[t];
    #pragma unroll
    for (int o = 16; o; o >>= 1)
        v += __shfl_down_sync(0xffffffffu, v, o);
    if ((t & 31) == 0) red[t >> 5] = v;
    __syncthreads();

    float* row = out + (size_t)b * NV;

    // Atomic histogram into the row; leader election via returned old.
    bool leader = false;
    if (my != PAD) {
        float old = atomicAdd(&row[my], 1.0f);
        leader = (old == 0.0f);
    }

    // s_add while atomics fly.
    if (t == 0) {
        int s = 0;
        #pragma unroll
        for (int i = 0; i < 16; i++) s += red[i];
        float avgdl = (float)s / (float)NB;
        float d_avg = (float)g_dl[b] / avgdl;
        s_add = 1.6f * (1.0f - 0.75f + 0.75f * d_avg);   // k*(1-b+b*d_avg)
    }
    __syncthreads();   // every thread held its atomic's return => all performed

    // BM25 transform: one writer per (row, token).
    if (leader) {
        float c = __ldcg(row + my);    // L2 read (bypass any stale L1 line)
        row[my] = c * 2.6f / (c + s_add);   // (k+1) = 2.6
    }
}

// ---------------------------------------------------------------------------
extern "C" void kernel_launch(void* const* d_in, const int* in_sizes, int n_in,
                              void* d_out, int out_size) {
    const int* ids = (const int*)d_in[0];
    float*     out = (float*)d_out;

    k_doclen<<<NB, 128>>>(ids);
    k_fill<<<FILL_BLOCKS, FILL_THREADS>>>((float4*)out);
    k_hist<<<NB, 512>>>(ids, out);
}

// round 13
// speedup vs baseline: 1.0691x; 1.0691x over previous
#include <cuda_runtime.h>
#include <cuda_bf16.h>
#include <stdint.h>

#define NB   512      // batch (docs)
#define NS   512      // seq len
#define NV   50265    // vocab
#define PAD  1
#define TOT  (NB * NV)          // 25,735,680 floats, divisible by 4
#define NV4  (TOT / 4)          // 6,433,920 float4

#define FILL_BLOCKS  1184       // 148 SMs x 8 -> perfectly balanced
#define FILL_THREADS 256

// Scratch (device globals only — no allocations allowed)
__device__ int g_dl[NB];    // doc lengths (non-pad token counts)

// ---------------------------------------------------------------------------
// Kernel 1: balanced zero-fill of the whole output + hidden doclen.
// 1184 blocks x 256 threads. Blocks 0..511 additionally compute the doc
// length of row b: 128 int4 loads issued BEFORE the store stream (held in
// registers, latency hidden under ~20us of stores), reduced at the end.
// ---------------------------------------------------------------------------
__global__ void __launch_bounds__(FILL_THREADS) k_fillplus(const int* __restrict__ ids,
                                                           float4* __restrict__ out4) {
    int b = blockIdx.x;
    int t = threadIdx.x;

    // Issue the doclen loads first (blocks 0..511, threads 0..127).
    int4 q = make_int4(PAD, PAD, PAD, PAD);
    if (b < NB && t < 128)
        q = ((const int4*)(ids + b * NS))[t];     // 128 x int4 = 512 ints

    // Balanced linear zero-fill (pure store stream, the DRAM-write floor).
    const float4 z4 = make_float4(0.f, 0.f, 0.f, 0.f);
    const int stride = FILL_BLOCKS * FILL_THREADS;  // 303,104
    for (int i = b * FILL_THREADS + t; i < NV4; i += stride)
        out4[i] = z4;

    // Doclen reduce (free: loads returned long ago).
    if (b < NB) {
        int cnt = (q.x != PAD) + (q.y != PAD) + (q.z != PAD) + (q.w != PAD);
        #pragma unroll
        for (int o = 16; o; o >>= 1)
            cnt += __shfl_down_sync(0xffffffffu, cnt, o);
        __shared__ int red[8];
        if ((t & 31) == 0) red[t >> 5] = cnt;     // warps 4..7 write 0
        __syncthreads();
        if (t == 0)
            g_dl[b] = red[0] + red[1] + red[2] + red[3];
    }
}

// ---------------------------------------------------------------------------
// Kernel 2: atomic histogram + BM25 transform. One block per row, 512 threads.
// Zeros are globally visible (kernel-ordering edge).
//   old = atomicAdd(&row[tok], 1.0f); leader = (old == 0)
//   sync; leader reads final count via __ldcg (L2) and writes f(count).
// ---------------------------------------------------------------------------
__global__ void __launch_bounds__(512) k_hist(const int* __restrict__ ids,
                                              float* __restrict__ out) {
    __shared__ int   red[16];
    __shared__ float s_add;

    int b = blockIdx.x;
    int t = threadIdx.x;

    int my = ids[b * NS + t];          // own token (coalesced)

    // avgdl: block-reduce the 512-entry g_dl array (L2 hits).
    int v = g_dl[t];
    #pragma unroll
    for (int o = 16; o; o >>= 1)
        v += __shfl_down_sync(0xffffffffu, v, o);
    if ((t & 31) == 0) red[t >> 5] = v;
    __syncthreads();

    float* row = out + (size_t)b * NV;

    // Atomic histogram into the row; leader election via returned old.
    bool leader = false;
    if (my != PAD) {
        float old = atomicAdd(&row[my], 1.0f);
        leader = (old == 0.0f);
    }

    // s_add while atomics fly.
    if (t == 0) {
        int s = 0;
        #pragma unroll
        for (int i = 0; i < 16; i++) s += red[i];
        float avgdl = (float)s / (float)NB;
        float d_avg = (float)g_dl[b] / avgdl;
        s_add = 1.6f * (1.0f - 0.75f + 0.75f * d_avg);   // k*(1-b+b*d_avg)
    }
    __syncthreads();   // every thread held its atomic's return => all performed

    // BM25 transform: one writer per (row, token).
    if (leader) {
        float c = __ldcg(row + my);    // L2 read (bypass any stale L1 line)
        row[my] = c * 2.6f / (c + s_add);   // (k+1) = 2.6
    }
}

// ---------------------------------------------------------------------------
extern "C" void kernel_launch(void* const* d_in, const int* in_sizes, int n_in,
                              void* d_out, int out_size) {
    const int* ids = (const int*)d_in[0];
    float*     out = (float*)d_out;

    k_fillplus<<<FILL_BLOCKS, FILL_THREADS>>>(ids, (float4*)out);
    k_hist<<<NB, 512>>>(ids, out);
}